// round 3
// baseline (speedup 1.0000x reference)
#include <cuda_runtime.h>
#include <cuda_bf16.h>

// y[i,h,ww] = sum_{kj,kh,l} w[i,kj,kh,l] * U[h+kj-1, kh, ww, l]   (zero pad on h+kj-1)
// U[ap,kh,b,l] = T(ap,kh,(b-1)%14, l+128) + T(ap,kh,b,l)
// T(ap,kh,b',c) = (0 <= b'+kh-1 < 14) ? x[c, ap, (b'+kh-2) mod 14] : 0

#define U_ELEMS (14 * 3 * 14 * 128)   // 75264
#define WSTR    1156                   // padded w_s row stride (floats), %4==0, %32==4
#define SMEM_FLOATS (16128 + 32 * WSTR)
#define SMEM_BYTES  (SMEM_FLOATS * 4)  // 212480 B

__device__ float g_U[U_ELEMS];

__global__ void build_u_kernel(const float* __restrict__ x) {
    int e = blockIdx.x * blockDim.x + threadIdx.x;   // 294*256 == 75264 exactly
    int l  = e & 127;
    int b  = (e >> 7) % 14;
    int kh = (e / (128 * 14)) % 3;
    int ap = e / (128 * 14 * 3);

    float val = 0.0f;
    // term: b' = b, channel l
    int t = b + kh - 1;
    if (t >= 0 && t < 14) {
        int wsrc = t - 1; if (wsrc < 0) wsrc += 14;
        val += x[l * 196 + ap * 14 + wsrc];
    }
    // term: b' = (b-1) mod 14, channel l+128
    int bm = b - 1; if (bm < 0) bm += 14;
    int t1 = bm + kh - 1;
    if (t1 >= 0 && t1 < 14) {
        int wsrc = t1 - 1; if (wsrc < 0) wsrc += 14;
        val += x[(l + 128) * 196 + ap * 14 + wsrc];
    }
    g_U[e] = val;
}

__global__ __launch_bounds__(256, 1)
void gemm_kernel(const float* __restrict__ w, float* __restrict__ y) {
    extern __shared__ float smem[];
    float* u_s = smem;            // [3][3][14][128] = 16128 floats (kj-slot holds ap=a-1+kj)
    float* w_s = smem + 16128;    // [32][WSTR], rows hold w[i0+i][0:1152]

    const int a  = blockIdx.x;    // 0..13 (h)
    const int i0 = blockIdx.y * 32;
    const int tid = threadIdx.x;

    // ---- stage U slice (3 ap rows; zero outside [0,14)) ----
    const float4* U4 = (const float4*)g_U;
    for (int idx = tid; idx < 16128 / 4; idx += 256) {
        int kj  = idx / 1344;            // 5376/4
        int rem = idx - kj * 1344;
        int ap  = a - 1 + kj;
        float4 v = make_float4(0.f, 0.f, 0.f, 0.f);
        if (ap >= 0 && ap < 14) v = U4[ap * 1344 + rem];
        ((float4*)u_s)[idx] = v;
    }
    // ---- stage w tile: 32 rows x 1152 ----
    const float4* W4 = (const float4*)w;
    for (int idx = tid; idx < 32 * 288; idx += 256) {   // 1152/4 = 288
        int i  = idx / 288;
        int kq = idx - i * 288;
        float4 v = W4[(i0 + i) * 288 + kq];
        *(float4*)(w_s + i * WSTR + kq * 4) = v;
    }
    __syncthreads();

    const int warp = tid >> 5;
    const int lane = tid & 31;

    float acc[14];
#pragma unroll
    for (int b = 0; b < 14; b++) acc[b] = 0.f;

    const int k0 = warp * 144;                       // split-K: 8 x 144 = 1152
    const float4* wp = (const float4*)(w_s + lane * WSTR + k0);
    const float4* u4 = (const float4*)u_s;

    for (int kk = 0; kk < 144; kk += 4) {
        float4 wv = wp[kk >> 2];
        int k = k0 + kk;
        int ub = ((k >> 7) * 1792 + (k & 127)) >> 2;  // float4 index into u_s for b=0
#pragma unroll
        for (int b = 0; b < 14; b++) {
            float4 uv = u4[ub + b * 32];              // warp-broadcast
            acc[b] = fmaf(wv.x, uv.x, acc[b]);
            acc[b] = fmaf(wv.y, uv.y, acc[b]);
            acc[b] = fmaf(wv.z, uv.z, acc[b]);
            acc[b] = fmaf(wv.w, uv.w, acc[b]);
        }
    }

    __syncthreads();
    // ---- cross-warp reduction: red[warp][b][lane] in u_s space ----
    float* red = u_s;
#pragma unroll
    for (int b = 0; b < 14; b++) red[(warp * 14 + b) * 32 + lane] = acc[b];
    __syncthreads();

    for (int o = tid; o < 14 * 32; o += 256) {
        int b = o >> 5;
        int i = o & 31;
        float s = 0.f;
#pragma unroll
        for (int wq = 0; wq < 8; wq++) s += red[(wq * 14 + b) * 32 + i];
        y[(i0 + i) * 196 + a * 14 + b] = s;
    }
}

extern "C" void kernel_launch(void* const* d_in, const int* in_sizes, int n_in,
                              void* d_out, int out_size) {
    const float* x = (const float*)d_in[0];
    const float* w = (const float*)d_in[1];
    float* y = (float*)d_out;

    cudaFuncSetAttribute(gemm_kernel,
                         cudaFuncAttributeMaxDynamicSharedMemorySize, SMEM_BYTES);

    build_u_kernel<<<294, 256>>>(x);
    gemm_kernel<<<dim3(14, 8), 256, SMEM_BYTES>>>(w, y);
}